// round 12
// baseline (speedup 1.0000x reference)
#include <cuda_runtime.h>
#include <math.h>

#define DMODEL 768
#define NHEADS 12
#define DK 64
#define BATCH 2
#define SEQ 4096
#define MTOT (BATCH*SEQ)   // 8192

// ---------------- scratch (no allocs allowed) ----------------
__device__ float g_q[(size_t)BATCH*NHEADS*SEQ*DK];     // [B,H,S,64]
__device__ float g_k[(size_t)BATCH*NHEADS*SEQ*DK];
__device__ float g_v[(size_t)BATCH*NHEADS*SEQ*DK];
__device__ float g_attn[(size_t)MTOT*DMODEL];          // [B*S, 768]

// ---------------- tf32 helpers ----------------
__device__ __forceinline__ unsigned f2tf(float x) {
    unsigned r;
    asm("cvt.rna.tf32.f32 %0, %1;" : "=r"(r) : "f"(x));
    return r;
}

__device__ __forceinline__ float4 cvt4(float4 v) {
    v.x = __uint_as_float(f2tf(v.x));
    v.y = __uint_as_float(f2tf(v.y));
    v.z = __uint_as_float(f2tf(v.z));
    v.w = __uint_as_float(f2tf(v.w));
    return v;
}

__device__ __forceinline__ void mma_tf32(float* c,
    unsigned a0, unsigned a1, unsigned a2, unsigned a3,
    unsigned b0, unsigned b1)
{
    asm("mma.sync.aligned.m16n8k8.row.col.f32.tf32.tf32.f32 "
        "{%0,%1,%2,%3}, {%4,%5,%6,%7}, {%8,%9}, {%0,%1,%2,%3};"
        : "+f"(c[0]), "+f"(c[1]), "+f"(c[2]), "+f"(c[3])
        : "r"(a0), "r"(a1), "r"(a2), "r"(a3), "r"(b0), "r"(b1));
}

// ---------------- GEMM core: Y = X @ W^T + bias ----------------
// Double-buffered DYNAMIC SMEM (static would exceed the 48KB limit),
// register prefetch, one barrier per k-iteration.
// LAYOUT 0: out[m][n] plain [M,768].
// LAYOUT 1: out in [B,H,S,DK]: m=(b*S+s), n=(h*64+d) -> ((b*H+h)*S+s)*64+d.
#define GTM 128
#define GTN 128
#define GTK 32
#define GSTR 36   // 32 + 4 pad: stride%32==4 -> conflict-free frag LDS

#define GEMM_SMEM_BYTES (2 * (GTM * GSTR + GTN * GSTR) * 4)   // 73728

template<int LAYOUT>
__device__ __forceinline__
void gemm_body(const float* __restrict__ X, const float* __restrict__ W,
               const float* __restrict__ bias, float* __restrict__ out)
{
    extern __shared__ float gsm[];
    float* Asb = gsm;                       // [2][GTM*GSTR]
    float* Bsb = gsm + 2 * GTM * GSTR;      // [2][GTN*GSTR]

    const int tid  = threadIdx.x;
    const int m0   = blockIdx.x * GTM;
    const int n0   = blockIdx.y * GTN;
    const int warp = tid >> 5, lane = tid & 31;
    const int g = lane >> 2, j = lane & 3;
    const int wm = (warp >> 2) * 64;   // 2 warps in M
    const int wn = (warp & 3) * 32;    // 4 warps in N

    const int sr  = tid >> 3;          // staging row base (advances by 32 per i)
    const int sc4 = tid & 7;

    float acc[4][4][4];
    #pragma unroll
    for (int a = 0; a < 4; a++)
        #pragma unroll
        for (int b = 0; b < 4; b++)
            #pragma unroll
            for (int c = 0; c < 4; c++) acc[a][b][c] = 0.f;

    float4 ra[4], rb[4];

    // prologue: load kt=0
    #pragma unroll
    for (int i = 0; i < 4; i++) {
        const int r = sr + i * 32;
        ra[i] = *(const float4*)(X + (size_t)(m0 + r) * DMODEL + sc4 * 4);
        rb[i] = *(const float4*)(W + (size_t)(n0 + r) * DMODEL + sc4 * 4);
    }
    #pragma unroll
    for (int i = 0; i < 4; i++) {
        const int r = sr + i * 32;
        *(float4*)(Asb + r * GSTR + sc4 * 4) = cvt4(ra[i]);
        *(float4*)(Bsb + r * GSTR + sc4 * 4) = cvt4(rb[i]);
    }
    __syncthreads();

    int cur = 0;
    for (int kt = 0; kt < DMODEL; kt += GTK) {
        const bool more = (kt + GTK < DMODEL);
        if (more) {
            #pragma unroll
            for (int i = 0; i < 4; i++) {
                const int r = sr + i * 32;
                ra[i] = *(const float4*)(X + (size_t)(m0 + r) * DMODEL + kt + GTK + sc4 * 4);
                rb[i] = *(const float4*)(W + (size_t)(n0 + r) * DMODEL + kt + GTK + sc4 * 4);
            }
        }

        const float* Ab = Asb + cur * GTM * GSTR;
        const float* Bb = Bsb + cur * GTN * GSTR;
        #pragma unroll
        for (int ks = 0; ks < 4; ks++) {
            const int k0 = ks * 8;
            unsigned a[4][4], b[4][2];
            #pragma unroll
            for (int im = 0; im < 4; im++) {
                const float* ap = Ab + (wm + im * 16) * GSTR + k0;
                a[im][0] = __float_as_uint(ap[g * GSTR + j]);
                a[im][1] = __float_as_uint(ap[(g + 8) * GSTR + j]);
                a[im][2] = __float_as_uint(ap[g * GSTR + j + 4]);
                a[im][3] = __float_as_uint(ap[(g + 8) * GSTR + j + 4]);
            }
            #pragma unroll
            for (int in_ = 0; in_ < 4; in_++) {
                const float* bp = Bb + (wn + in_ * 8 + g) * GSTR + k0;
                b[in_][0] = __float_as_uint(bp[j]);
                b[in_][1] = __float_as_uint(bp[j + 4]);
            }
            #pragma unroll
            for (int im = 0; im < 4; im++)
                #pragma unroll
                for (int in_ = 0; in_ < 4; in_++)
                    mma_tf32(acc[im][in_], a[im][0], a[im][1], a[im][2], a[im][3],
                             b[in_][0], b[in_][1]);
        }

        if (more) {
            const int nxt = cur ^ 1;
            float* An = Asb + nxt * GTM * GSTR;
            float* Bn = Bsb + nxt * GTN * GSTR;
            #pragma unroll
            for (int i = 0; i < 4; i++) {
                const int r = sr + i * 32;
                *(float4*)(An + r * GSTR + sc4 * 4) = cvt4(ra[i]);
                *(float4*)(Bn + r * GSTR + sc4 * 4) = cvt4(rb[i]);
            }
        }
        __syncthreads();
        cur ^= 1;
    }

    // epilogue
    #pragma unroll
    for (int im = 0; im < 4; im++) {
        const int r0 = m0 + wm + im * 16 + g;
        #pragma unroll
        for (int in_ = 0; in_ < 4; in_++) {
            const int n = n0 + wn + in_ * 8 + j * 2;
            const float bv0 = __ldg(bias + n), bv1 = __ldg(bias + n + 1);
            float v00 = acc[im][in_][0] + bv0;
            float v01 = acc[im][in_][1] + bv1;
            float v10 = acc[im][in_][2] + bv0;
            float v11 = acc[im][in_][3] + bv1;
            if (LAYOUT == 0) {
                *(float2*)(out + (size_t)r0 * DMODEL + n)       = make_float2(v00, v01);
                *(float2*)(out + (size_t)(r0 + 8) * DMODEL + n) = make_float2(v10, v11);
            } else {
                const int b_ = r0 >> 12;           // SEQ = 4096
                const int s0 = r0 & (SEQ - 1);     // tile never crosses batch boundary
                const int h_ = n >> 6;
                const int d  = n & (DK - 1);
                size_t o0 = (((size_t)(b_ * NHEADS + h_)) * SEQ + s0) * DK + d;
                *(float2*)(out + o0)            = make_float2(v00, v01);
                *(float2*)(out + o0 + 8 * DK)   = make_float2(v10, v11);
            }
        }
    }
}

// Fused Q/K/V projection: gridDim.z = 3 selects the (X, W, bias, out) set.
__global__ __launch_bounds__(256, 1)
void gemm_qkv(const float* __restrict__ Xq, const float* __restrict__ Wq,
              const float* __restrict__ bq, float* __restrict__ oq,
              const float* __restrict__ Xk, const float* __restrict__ Wk,
              const float* __restrict__ bk, float* __restrict__ ok,
              const float* __restrict__ Xv, const float* __restrict__ Wv,
              const float* __restrict__ bv, float* __restrict__ ov)
{
    const float *X, *W, *bias;
    float* out;
    if (blockIdx.z == 0)      { X = Xq; W = Wq; bias = bq; out = oq; }
    else if (blockIdx.z == 1) { X = Xk; W = Wk; bias = bk; out = ok; }
    else                      { X = Xv; W = Wv; bias = bv; out = ov; }
    gemm_body<1>(X, W, bias, out);
}

__global__ __launch_bounds__(256, 1)
void gemm_out(const float* __restrict__ X, const float* __restrict__ W,
              const float* __restrict__ bias, float* __restrict__ out)
{
    gemm_body<0>(X, W, bias, out);
}

// ---------------- flash attention ----------------
// grid (SEQ/128, B*H), 256 threads = 8 warps; warp owns 16 query rows (1 m16 tile).
// occ 2 (no spills: ~107 regs/thread peak). Double-buffered K/V, register
// prefetch with split K/V live ranges, PV A-fragments from S-fragments via
// quad shuffles (no P SMEM round-trip), single barrier per KV iteration.
// Softmax in base-2 domain: Q pre-scaled by (1/sqrt(dk))*log2(e), exp2f used
// throughout -> identical probabilities, one fewer FMUL per exp.
#define BM 128
#define BN 64
#define QSTR 68   // 64+4: stride%32==4 -> conflict-free frag LDS
#define VSTR 72   // 64+8: stride%32==8 -> conflict-free V (B-operand) frag LDS

#define ATT_SMEM_FLOATS (BM*QSTR + 2*BN*QSTR + 2*BN*VSTR)
#define ATT_SMEM_BYTES  (ATT_SMEM_FLOATS * 4)   // 106496; x2 CTAs = 208 KB <= 228 KB

__global__ __launch_bounds__(256, 2)
void attn_kernel(const float* __restrict__ gq, const float* __restrict__ gk,
                 const float* __restrict__ gv, float* __restrict__ gout)
{
    extern __shared__ float sm[];
    float* Qs  = sm;                         // [128][68]
    float* Ks0 = Qs + BM * QSTR;             // [2][64][68]
    float* Vs0 = Ks0 + 2 * BN * QSTR;        // [2][64][72]

    const int tid  = threadIdx.x;
    const int warp = tid >> 5, lane = tid & 31;
    const int g = lane >> 2, j = lane & 3;
    const int bh = blockIdx.y;               // b*NHEADS + h
    const int q0 = blockIdx.x * BM;
    const size_t base = (size_t)bh * SEQ * DK;
    const float scale = 0.125f * 1.4426950408889634f;  // (1/sqrt(64)) * log2(e)

    // K/V staging: 64 rows x 16 float4 = 1024 slots, 4 per thread
    const int kr  = tid >> 4;                // base row, advances by 16 per i
    const int kc4 = tid & 15;

    // stage Q tile (scaled, tf32): 2048 float4 slots, 8 per thread
    #pragma unroll
    for (int i = 0; i < 8; i++) {
        int slot = tid + i * 256;
        int r  = slot >> 4;
        int c4 = slot & 15;
        float4 v = *(const float4*)(gq + base + (size_t)(q0 + r) * DK + c4 * 4);
        v.x = __uint_as_float(f2tf(v.x * scale));
        v.y = __uint_as_float(f2tf(v.y * scale));
        v.z = __uint_as_float(f2tf(v.z * scale));
        v.w = __uint_as_float(f2tf(v.w * scale));
        *(float4*)(Qs + r * QSTR + c4 * 4) = v;
    }

    float o[8][4];
    #pragma unroll
    for (int a = 0; a < 8; a++)
        #pragma unroll
        for (int c = 0; c < 4; c++) o[a][c] = 0.f;
    float m0r = -INFINITY, m1r = -INFINITY;
    float l0r = 0.f, l1r = 0.f;

    const float* Qw = Qs + (warp * 16) * QSTR;
    const unsigned FULL = 0xffffffffu;
    const int srcA = (lane & 28) | (j >> 1);
    const int srcB = srcA | 2;
    const bool hb = (j & 1);

    // prologue: stage K/V tile 0 into buffer 0
    {
        float4 rk[4], rv[4];
        #pragma unroll
        for (int i = 0; i < 4; i++) {
            const int r = kr + i * 16;
            size_t go = base + (size_t)r * DK + kc4 * 4;
            rk[i] = *(const float4*)(gk + go);
            rv[i] = *(const float4*)(gv + go);
        }
        #pragma unroll
        for (int i = 0; i < 4; i++) {
            const int r = kr + i * 16;
            *(float4*)(Ks0 + r * QSTR + kc4 * 4) = cvt4(rk[i]);
            *(float4*)(Vs0 + r * VSTR + kc4 * 4) = cvt4(rv[i]);
        }
    }
    __syncthreads();

    int cur = 0;
    for (int t = 0; t < SEQ / BN; t++) {
        const bool more = (t + 1 < SEQ / BN);
        const float* Ks = Ks0 + cur * BN * QSTR;
        const float* Vs = Vs0 + cur * BN * VSTR;
        float* Kn = Ks0 + (cur ^ 1) * BN * QSTR;
        float* Vn = Vs0 + (cur ^ 1) * BN * VSTR;

        // prefetch next K tile (latency hidden under QK mma)
        float4 rk[4];
        if (more) {
            #pragma unroll
            for (int i = 0; i < 4; i++) {
                const int r = kr + i * 16;
                rk[i] = *(const float4*)(gk + base + (size_t)((t + 1) * BN + r) * DK + kc4 * 4);
            }
        }

        // S = Q K^T (scale+log2e folded into Q); warp: 16 rows x 64 kv cols
        float s[8][4];
        #pragma unroll
        for (int a = 0; a < 8; a++)
            #pragma unroll
            for (int c = 0; c < 4; c++) s[a][c] = 0.f;

        #pragma unroll
        for (int ks = 0; ks < 8; ks++) {
            const int k0 = ks * 8;
            unsigned a0 = __float_as_uint(Qw[g * QSTR + k0 + j]);
            unsigned a1 = __float_as_uint(Qw[(g + 8) * QSTR + k0 + j]);
            unsigned a2 = __float_as_uint(Qw[g * QSTR + k0 + j + 4]);
            unsigned a3 = __float_as_uint(Qw[(g + 8) * QSTR + k0 + j + 4]);
            #pragma unroll
            for (int nf = 0; nf < 8; nf++) {
                unsigned b0 = __float_as_uint(Ks[(nf * 8 + g) * QSTR + k0 + j]);
                unsigned b1 = __float_as_uint(Ks[(nf * 8 + g) * QSTR + k0 + j + 4]);
                mma_tf32(s[nf], a0, a1, a2, a3, b0, b1);
            }
        }

        // store prefetched K; prefetch next V (hidden under softmax + PV mma)
        float4 rv[4];
        if (more) {
            #pragma unroll
            for (int i = 0; i < 4; i++) {
                const int r = kr + i * 16;
                *(float4*)(Kn + r * QSTR + kc4 * 4) = cvt4(rk[i]);
            }
            #pragma unroll
            for (int i = 0; i < 4; i++) {
                const int r = kr + i * 16;
                rv[i] = *(const float4*)(gv + base + (size_t)((t + 1) * BN + r) * DK + kc4 * 4);
            }
        }

        // online softmax (base-2): rows g (c0,c1) and g+8 (c2,c3); quad reduce
        float mx0 = -INFINITY, mx1 = -INFINITY;
        #pragma unroll
        for (int nf = 0; nf < 8; nf++) {
            mx0 = fmaxf(mx0, fmaxf(s[nf][0], s[nf][1]));
            mx1 = fmaxf(mx1, fmaxf(s[nf][2], s[nf][3]));
        }
        mx0 = fmaxf(mx0, __shfl_xor_sync(FULL, mx0, 1));
        mx0 = fmaxf(mx0, __shfl_xor_sync(FULL, mx0, 2));
        mx1 = fmaxf(mx1, __shfl_xor_sync(FULL, mx1, 1));
        mx1 = fmaxf(mx1, __shfl_xor_sync(FULL, mx1, 2));

        const float mn0 = fmaxf(m0r, mx0);
        const float mn1 = fmaxf(m1r, mx1);
        const float corr0 = exp2f(m0r - mn0);   // exp2(-inf)=0 first iter
        const float corr1 = exp2f(m1r - mn1);
        m0r = mn0; m1r = mn1;

        float sum0 = 0.f, sum1 = 0.f;
        #pragma unroll
        for (int nf = 0; nf < 8; nf++) {
            s[nf][0] = exp2f(s[nf][0] - mn0);
            s[nf][1] = exp2f(s[nf][1] - mn0);
            s[nf][2] = exp2f(s[nf][2] - mn1);
            s[nf][3] = exp2f(s[nf][3] - mn1);
            sum0 += s[nf][0] + s[nf][1];
            sum1 += s[nf][2] + s[nf][3];
        }
        sum0 += __shfl_xor_sync(FULL, sum0, 1);
        sum0 += __shfl_xor_sync(FULL, sum0, 2);
        sum1 += __shfl_xor_sync(FULL, sum1, 1);
        sum1 += __shfl_xor_sync(FULL, sum1, 2);
        l0r = l0r * corr0 + sum0;
        l1r = l1r * corr1 + sum1;

        #pragma unroll
        for (int nf = 0; nf < 8; nf++) {
            o[nf][0] *= corr0; o[nf][1] *= corr0;
            o[nf][2] *= corr1; o[nf][3] *= corr1;
        }

        // O += P @ V. PV A-fragments from S-fragments via quad shuffles:
        // lane (g,j) needs P[g][ks*8+j] -> held by lane (g, j>>1) as s[ks][j&1]
        #pragma unroll
        for (int ks = 0; ks < 8; ks++) {
            const int k0 = ks * 8;
            float p0 = __shfl_sync(FULL, s[ks][0], srcA);
            float p1 = __shfl_sync(FULL, s[ks][1], srcA);
            float p2 = __shfl_sync(FULL, s[ks][2], srcA);
            float p3 = __shfl_sync(FULL, s[ks][3], srcA);
            float u0 = __shfl_sync(FULL, s[ks][0], srcB);
            float u1 = __shfl_sync(FULL, s[ks][1], srcB);
            float u2 = __shfl_sync(FULL, s[ks][2], srcB);
            float u3 = __shfl_sync(FULL, s[ks][3], srcB);
            unsigned a0 = f2tf(hb ? p1 : p0);
            unsigned a1 = f2tf(hb ? p3 : p2);
            unsigned a2 = f2tf(hb ? u1 : u0);
            unsigned a3 = f2tf(hb ? u3 : u2);
            #pragma unroll
            for (int nf = 0; nf < 8; nf++) {
                unsigned b0 = __float_as_uint(Vs[(k0 + j) * VSTR + nf * 8 + g]);
                unsigned b1 = __float_as_uint(Vs[(k0 + j + 4) * VSTR + nf * 8 + g]);
                mma_tf32(o[nf], a0, a1, a2, a3, b0, b1);
            }
        }

        // store prefetched V; single barrier per iteration
        if (more) {
            #pragma unroll
            for (int i = 0; i < 4; i++) {
                const int r = kr + i * 16;
                *(float4*)(Vn + r * VSTR + kc4 * 4) = cvt4(rv[i]);
            }
        }
        __syncthreads();
        cur ^= 1;
    }

    // normalize + write to [B*S, 768] attn scratch
    const float inv0 = 1.f / l0r;
    const float inv1 = 1.f / l1r;
    const int b_ = bh / NHEADS, h_ = bh % NHEADS;
    const int row0 = q0 + warp * 16 + g;
    const size_t obase = ((size_t)b_ * SEQ) * DMODEL + (size_t)h_ * DK;
    #pragma unroll
    for (int nf = 0; nf < 8; nf++) {
        const int c = nf * 8 + j * 2;
        *(float2*)(gout + obase + (size_t)row0 * DMODEL + c) =
            make_float2(o[nf][0] * inv0, o[nf][1] * inv0);
        *(float2*)(gout + obase + (size_t)(row0 + 8) * DMODEL + c) =
            make_float2(o[nf][2] * inv1, o[nf][3] * inv1);
    }
}

// ---------------- launch ----------------
extern "C" void kernel_launch(void* const* d_in, const int* in_sizes, int n_in,
                              void* d_out, int out_size)
{
    (void)in_sizes; (void)n_in; (void)out_size;
    const float* Q  = (const float*)d_in[0];
    const float* K  = (const float*)d_in[1];
    const float* V  = (const float*)d_in[2];
    const float* Wq = (const float*)d_in[3];
    const float* bq = (const float*)d_in[4];
    const float* Wk = (const float*)d_in[5];
    const float* bk = (const float*)d_in[6];
    const float* Wv = (const float*)d_in[7];
    const float* bv = (const float*)d_in[8];
    const float* Wo = (const float*)d_in[9];
    const float* bo = (const float*)d_in[10];
    float* out = (float*)d_out;

    float *pq, *pk, *pv, *pa;
    cudaGetSymbolAddress((void**)&pq, g_q);
    cudaGetSymbolAddress((void**)&pk, g_k);
    cudaGetSymbolAddress((void**)&pv, g_v);
    cudaGetSymbolAddress((void**)&pa, g_attn);

    cudaFuncSetAttribute(gemm_qkv,
                         cudaFuncAttributeMaxDynamicSharedMemorySize, GEMM_SMEM_BYTES);
    cudaFuncSetAttribute(gemm_out,
                         cudaFuncAttributeMaxDynamicSharedMemorySize, GEMM_SMEM_BYTES);
    cudaFuncSetAttribute(attn_kernel,
                         cudaFuncAttributeMaxDynamicSharedMemorySize, ATT_SMEM_BYTES);

    // Fused Q/K/V projections: grid (64, 6, 3) -> 1152 CTAs, single wave-tail.
    dim3 qkvgrid(MTOT / GTM, DMODEL / GTN, 3);
    gemm_qkv<<<qkvgrid, 256, GEMM_SMEM_BYTES>>>(Q, Wq, bq, pq,
                                                K, Wk, bk, pk,
                                                V, Wv, bv, pv);

    attn_kernel<<<dim3(SEQ / BM, BATCH * NHEADS), 256, ATT_SMEM_BYTES>>>(pq, pk, pv, pa);

    dim3 ogrid(MTOT / GTM, DMODEL / GTN);   // (64, 6)
    gemm_out<<<ogrid, 256, GEMM_SMEM_BYTES>>>(pa, Wo, bo, out);
}

// round 17
// speedup vs baseline: 1.0416x; 1.0416x over previous
#include <cuda_runtime.h>
#include <math.h>

#define DMODEL 768
#define NHEADS 12
#define DK 64
#define BATCH 2
#define SEQ 4096
#define MTOT (BATCH*SEQ)   // 8192

// ---------------- scratch (no allocs allowed) ----------------
__device__ float g_q[(size_t)BATCH*NHEADS*SEQ*DK];     // [B,H,S,64]
__device__ float g_k[(size_t)BATCH*NHEADS*SEQ*DK];
__device__ float g_v[(size_t)BATCH*NHEADS*SEQ*DK];
__device__ float g_attn[(size_t)MTOT*DMODEL];          // [B*S, 768]

// ---------------- tf32 helpers ----------------
__device__ __forceinline__ unsigned f2tf(float x) {
    unsigned r;
    asm("cvt.rna.tf32.f32 %0, %1;" : "=r"(r) : "f"(x));
    return r;
}

__device__ __forceinline__ float4 cvt4(float4 v) {
    v.x = __uint_as_float(f2tf(v.x));
    v.y = __uint_as_float(f2tf(v.y));
    v.z = __uint_as_float(f2tf(v.z));
    v.w = __uint_as_float(f2tf(v.w));
    return v;
}

__device__ __forceinline__ void mma_tf32(float* c,
    unsigned a0, unsigned a1, unsigned a2, unsigned a3,
    unsigned b0, unsigned b1)
{
    asm("mma.sync.aligned.m16n8k8.row.col.f32.tf32.tf32.f32 "
        "{%0,%1,%2,%3}, {%4,%5,%6,%7}, {%8,%9}, {%0,%1,%2,%3};"
        : "+f"(c[0]), "+f"(c[1]), "+f"(c[2]), "+f"(c[3])
        : "r"(a0), "r"(a1), "r"(a2), "r"(a3), "r"(b0), "r"(b1));
}

// ---------------- GEMM core: Y = X @ W^T + bias ----------------
// Double-buffered DYNAMIC SMEM, register prefetch, one barrier per k-iter.
// LAYOUT 0: out[m][n] plain [M,768].
// LAYOUT 1: out in [B,H,S,DK]: m=(b*S+s), n=(h*64+d) -> ((b*H+h)*S+s)*64+d.
#define GTM 128
#define GTN 128
#define GTK 32
#define GSTR 36   // 32 + 4 pad: stride%32==4 -> conflict-free frag LDS

#define GEMM_SMEM_BYTES (2 * (GTM * GSTR + GTN * GSTR) * 4)   // 73728

template<int LAYOUT>
__device__ __forceinline__
void gemm_body(const float* __restrict__ X, const float* __restrict__ W,
               const float* __restrict__ bias, float* __restrict__ out)
{
    extern __shared__ float gsm[];
    float* Asb = gsm;                       // [2][GTM*GSTR]
    float* Bsb = gsm + 2 * GTM * GSTR;      // [2][GTN*GSTR]

    const int tid  = threadIdx.x;
    const int m0   = blockIdx.x * GTM;
    const int n0   = blockIdx.y * GTN;
    const int warp = tid >> 5, lane = tid & 31;
    const int g = lane >> 2, j = lane & 3;
    const int wm = (warp >> 2) * 64;   // 2 warps in M
    const int wn = (warp & 3) * 32;    // 4 warps in N

    const int sr  = tid >> 3;          // staging row base (advances by 32 per i)
    const int sc4 = tid & 7;

    float acc[4][4][4];
    #pragma unroll
    for (int a = 0; a < 4; a++)
        #pragma unroll
        for (int b = 0; b < 4; b++)
            #pragma unroll
            for (int c = 0; c < 4; c++) acc[a][b][c] = 0.f;

    float4 ra[4], rb[4];

    // prologue: load kt=0
    #pragma unroll
    for (int i = 0; i < 4; i++) {
        const int r = sr + i * 32;
        ra[i] = *(const float4*)(X + (size_t)(m0 + r) * DMODEL + sc4 * 4);
        rb[i] = *(const float4*)(W + (size_t)(n0 + r) * DMODEL + sc4 * 4);
    }
    #pragma unroll
    for (int i = 0; i < 4; i++) {
        const int r = sr + i * 32;
        *(float4*)(Asb + r * GSTR + sc4 * 4) = cvt4(ra[i]);
        *(float4*)(Bsb + r * GSTR + sc4 * 4) = cvt4(rb[i]);
    }
    __syncthreads();

    int cur = 0;
    for (int kt = 0; kt < DMODEL; kt += GTK) {
        const bool more = (kt + GTK < DMODEL);
        if (more) {
            #pragma unroll
            for (int i = 0; i < 4; i++) {
                const int r = sr + i * 32;
                ra[i] = *(const float4*)(X + (size_t)(m0 + r) * DMODEL + kt + GTK + sc4 * 4);
                rb[i] = *(const float4*)(W + (size_t)(n0 + r) * DMODEL + kt + GTK + sc4 * 4);
            }
        }

        const float* Ab = Asb + cur * GTM * GSTR;
        const float* Bb = Bsb + cur * GTN * GSTR;
        #pragma unroll
        for (int ks = 0; ks < 4; ks++) {
            const int k0 = ks * 8;
            unsigned a[4][4], b[4][2];
            #pragma unroll
            for (int im = 0; im < 4; im++) {
                const float* ap = Ab + (wm + im * 16) * GSTR + k0;
                a[im][0] = __float_as_uint(ap[g * GSTR + j]);
                a[im][1] = __float_as_uint(ap[(g + 8) * GSTR + j]);
                a[im][2] = __float_as_uint(ap[g * GSTR + j + 4]);
                a[im][3] = __float_as_uint(ap[(g + 8) * GSTR + j + 4]);
            }
            #pragma unroll
            for (int in_ = 0; in_ < 4; in_++) {
                const float* bp = Bb + (wn + in_ * 8 + g) * GSTR + k0;
                b[in_][0] = __float_as_uint(bp[j]);
                b[in_][1] = __float_as_uint(bp[j + 4]);
            }
            #pragma unroll
            for (int im = 0; im < 4; im++)
                #pragma unroll
                for (int in_ = 0; in_ < 4; in_++)
                    mma_tf32(acc[im][in_], a[im][0], a[im][1], a[im][2], a[im][3],
                             b[in_][0], b[in_][1]);
        }

        if (more) {
            const int nxt = cur ^ 1;
            float* An = Asb + nxt * GTM * GSTR;
            float* Bn = Bsb + nxt * GTN * GSTR;
            #pragma unroll
            for (int i = 0; i < 4; i++) {
                const int r = sr + i * 32;
                *(float4*)(An + r * GSTR + sc4 * 4) = cvt4(ra[i]);
                *(float4*)(Bn + r * GSTR + sc4 * 4) = cvt4(rb[i]);
            }
        }
        __syncthreads();
        cur ^= 1;
    }

    // epilogue
    #pragma unroll
    for (int im = 0; im < 4; im++) {
        const int r0 = m0 + wm + im * 16 + g;
        #pragma unroll
        for (int in_ = 0; in_ < 4; in_++) {
            const int n = n0 + wn + in_ * 8 + j * 2;
            const float bv0 = __ldg(bias + n), bv1 = __ldg(bias + n + 1);
            float v00 = acc[im][in_][0] + bv0;
            float v01 = acc[im][in_][1] + bv1;
            float v10 = acc[im][in_][2] + bv0;
            float v11 = acc[im][in_][3] + bv1;
            if (LAYOUT == 0) {
                *(float2*)(out + (size_t)r0 * DMODEL + n)       = make_float2(v00, v01);
                *(float2*)(out + (size_t)(r0 + 8) * DMODEL + n) = make_float2(v10, v11);
            } else {
                const int b_ = r0 >> 12;           // SEQ = 4096
                const int s0 = r0 & (SEQ - 1);     // tile never crosses batch boundary
                const int h_ = n >> 6;
                const int d  = n & (DK - 1);
                size_t o0 = (((size_t)(b_ * NHEADS + h_)) * SEQ + s0) * DK + d;
                *(float2*)(out + o0)            = make_float2(v00, v01);
                *(float2*)(out + o0 + 8 * DK)   = make_float2(v10, v11);
            }
        }
    }
}

// Fused Q/K/V projection: gridDim.z = 3 selects the (X, W, bias, out) set.
__global__ __launch_bounds__(256, 1)
void gemm_qkv(const float* __restrict__ Xq, const float* __restrict__ Wq,
              const float* __restrict__ bq, float* __restrict__ oq,
              const float* __restrict__ Xk, const float* __restrict__ Wk,
              const float* __restrict__ bk, float* __restrict__ ok,
              const float* __restrict__ Xv, const float* __restrict__ Wv,
              const float* __restrict__ bv, float* __restrict__ ov)
{
    const float *X, *W, *bias;
    float* out;
    if (blockIdx.z == 0)      { X = Xq; W = Wq; bias = bq; out = oq; }
    else if (blockIdx.z == 1) { X = Xk; W = Wk; bias = bk; out = ok; }
    else                      { X = Xv; W = Wv; bias = bv; out = ov; }
    gemm_body<1>(X, W, bias, out);
}

__global__ __launch_bounds__(256, 1)
void gemm_out(const float* __restrict__ X, const float* __restrict__ W,
              const float* __restrict__ bias, float* __restrict__ out)
{
    gemm_body<0>(X, W, bias, out);
}

// ---------------- flash attention ----------------
// BM=256, 512 threads (16 warps), occ 1. Same 16-rows-per-warp inner loop;
// per-SM warp count unchanged (16) but K/V staging bytes, barriers, and
// chip-wide K/V DRAM traffic all halve (each CTA amortizes its K/V stream
// over 256 q-rows instead of 128).
#define BM 256
#define ATT_THREADS 512
#define BN 64
#define QSTR 68   // 64+4: stride%32==4 -> conflict-free frag LDS
#define VSTR 72   // 64+8: stride%32==8 -> conflict-free V (B-operand) frag LDS

#define ATT_SMEM_FLOATS (BM*QSTR + 2*BN*QSTR + 2*BN*VSTR)
#define ATT_SMEM_BYTES  (ATT_SMEM_FLOATS * 4)   // 141312 <= 227KB (occ 1)

__global__ __launch_bounds__(ATT_THREADS, 1)
void attn_kernel(const float* __restrict__ gq, const float* __restrict__ gk,
                 const float* __restrict__ gv, float* __restrict__ gout)
{
    extern __shared__ float sm[];
    float* Qs  = sm;                         // [256][68]
    float* Ks0 = Qs + BM * QSTR;             // [2][64][68]
    float* Vs0 = Ks0 + 2 * BN * QSTR;        // [2][64][72]

    const int tid  = threadIdx.x;
    const int warp = tid >> 5, lane = tid & 31;
    const int g = lane >> 2, j = lane & 3;
    const int bh = blockIdx.y;               // b*NHEADS + h
    const int q0 = blockIdx.x * BM;
    const size_t base = (size_t)bh * SEQ * DK;
    const float scale = 0.125f * 1.4426950408889634f;  // (1/sqrt(64)) * log2(e)

    // K/V staging: 64 rows x 16 float4 = 1024 slots, 2 per thread
    const int kr  = tid >> 4;                // base row 0..31, advances by 32 per i
    const int kc4 = tid & 15;

    // stage Q tile (scaled, tf32): 256 rows x 16 float4 = 4096 slots, 8 per thread
    #pragma unroll
    for (int i = 0; i < 8; i++) {
        int slot = tid + i * ATT_THREADS;
        int r  = slot >> 4;
        int c4 = slot & 15;
        float4 v = *(const float4*)(gq + base + (size_t)(q0 + r) * DK + c4 * 4);
        v.x = __uint_as_float(f2tf(v.x * scale));
        v.y = __uint_as_float(f2tf(v.y * scale));
        v.z = __uint_as_float(f2tf(v.z * scale));
        v.w = __uint_as_float(f2tf(v.w * scale));
        *(float4*)(Qs + r * QSTR + c4 * 4) = v;
    }

    float o[8][4];
    #pragma unroll
    for (int a = 0; a < 8; a++)
        #pragma unroll
        for (int c = 0; c < 4; c++) o[a][c] = 0.f;
    float m0r = -INFINITY, m1r = -INFINITY;
    float l0r = 0.f, l1r = 0.f;

    const float* Qw = Qs + (warp * 16) * QSTR;
    const unsigned FULL = 0xffffffffu;
    const int srcA = (lane & 28) | (j >> 1);
    const int srcB = srcA | 2;
    const bool hb = (j & 1);

    // prologue: stage K/V tile 0 into buffer 0
    {
        float4 rk[2], rv[2];
        #pragma unroll
        for (int i = 0; i < 2; i++) {
            const int r = kr + i * 32;
            size_t go = base + (size_t)r * DK + kc4 * 4;
            rk[i] = *(const float4*)(gk + go);
            rv[i] = *(const float4*)(gv + go);
        }
        #pragma unroll
        for (int i = 0; i < 2; i++) {
            const int r = kr + i * 32;
            *(float4*)(Ks0 + r * QSTR + kc4 * 4) = cvt4(rk[i]);
            *(float4*)(Vs0 + r * VSTR + kc4 * 4) = cvt4(rv[i]);
        }
    }
    __syncthreads();

    int cur = 0;
    for (int t = 0; t < SEQ / BN; t++) {
        const bool more = (t + 1 < SEQ / BN);
        const float* Ks = Ks0 + cur * BN * QSTR;
        const float* Vs = Vs0 + cur * BN * VSTR;
        float* Kn = Ks0 + (cur ^ 1) * BN * QSTR;
        float* Vn = Vs0 + (cur ^ 1) * BN * VSTR;

        // prefetch next K tile (latency hidden under QK mma)
        float4 rk[2];
        if (more) {
            #pragma unroll
            for (int i = 0; i < 2; i++) {
                const int r = kr + i * 32;
                rk[i] = *(const float4*)(gk + base + (size_t)((t + 1) * BN + r) * DK + kc4 * 4);
            }
        }

        // S = Q K^T (scale+log2e folded into Q); warp: 16 rows x 64 kv cols
        float s[8][4];
        #pragma unroll
        for (int a = 0; a < 8; a++)
            #pragma unroll
            for (int c = 0; c < 4; c++) s[a][c] = 0.f;

        #pragma unroll
        for (int ks = 0; ks < 8; ks++) {
            const int k0 = ks * 8;
            unsigned a0 = __float_as_uint(Qw[g * QSTR + k0 + j]);
            unsigned a1 = __float_as_uint(Qw[(g + 8) * QSTR + k0 + j]);
            unsigned a2 = __float_as_uint(Qw[g * QSTR + k0 + j + 4]);
            unsigned a3 = __float_as_uint(Qw[(g + 8) * QSTR + k0 + j + 4]);
            #pragma unroll
            for (int nf = 0; nf < 8; nf++) {
                unsigned b0 = __float_as_uint(Ks[(nf * 8 + g) * QSTR + k0 + j]);
                unsigned b1 = __float_as_uint(Ks[(nf * 8 + g) * QSTR + k0 + j + 4]);
                mma_tf32(s[nf], a0, a1, a2, a3, b0, b1);
            }
        }

        // store prefetched K; prefetch next V (hidden under softmax + PV mma)
        float4 rv[2];
        if (more) {
            #pragma unroll
            for (int i = 0; i < 2; i++) {
                const int r = kr + i * 32;
                *(float4*)(Kn + r * QSTR + kc4 * 4) = cvt4(rk[i]);
            }
            #pragma unroll
            for (int i = 0; i < 2; i++) {
                const int r = kr + i * 32;
                rv[i] = *(const float4*)(gv + base + (size_t)((t + 1) * BN + r) * DK + kc4 * 4);
            }
        }

        // online softmax (base-2): rows g (c0,c1) and g+8 (c2,c3); quad reduce
        float mx0 = -INFINITY, mx1 = -INFINITY;
        #pragma unroll
        for (int nf = 0; nf < 8; nf++) {
            mx0 = fmaxf(mx0, fmaxf(s[nf][0], s[nf][1]));
            mx1 = fmaxf(mx1, fmaxf(s[nf][2], s[nf][3]));
        }
        mx0 = fmaxf(mx0, __shfl_xor_sync(FULL, mx0, 1));
        mx0 = fmaxf(mx0, __shfl_xor_sync(FULL, mx0, 2));
        mx1 = fmaxf(mx1, __shfl_xor_sync(FULL, mx1, 1));
        mx1 = fmaxf(mx1, __shfl_xor_sync(FULL, mx1, 2));

        const float mn0 = fmaxf(m0r, mx0);
        const float mn1 = fmaxf(m1r, mx1);
        const float corr0 = exp2f(m0r - mn0);   // exp2(-inf)=0 first iter
        const float corr1 = exp2f(m1r - mn1);
        m0r = mn0; m1r = mn1;

        float sum0 = 0.f, sum1 = 0.f;
        #pragma unroll
        for (int nf = 0; nf < 8; nf++) {
            s[nf][0] = exp2f(s[nf][0] - mn0);
            s[nf][1] = exp2f(s[nf][1] - mn0);
            s[nf][2] = exp2f(s[nf][2] - mn1);
            s[nf][3] = exp2f(s[nf][3] - mn1);
            sum0 += s[nf][0] + s[nf][1];
            sum1 += s[nf][2] + s[nf][3];
        }
        sum0 += __shfl_xor_sync(FULL, sum0, 1);
        sum0 += __shfl_xor_sync(FULL, sum0, 2);
        sum1 += __shfl_xor_sync(FULL, sum1, 1);
        sum1 += __shfl_xor_sync(FULL, sum1, 2);
        l0r = l0r * corr0 + sum0;
        l1r = l1r * corr1 + sum1;

        #pragma unroll
        for (int nf = 0; nf < 8; nf++) {
            o[nf][0] *= corr0; o[nf][1] *= corr0;
            o[nf][2] *= corr1; o[nf][3] *= corr1;
        }

        // O += P @ V. PV A-fragments from S-fragments via quad shuffles:
        // lane (g,j) needs P[g][ks*8+j] -> held by lane (g, j>>1) as s[ks][j&1]
        #pragma unroll
        for (int ks = 0; ks < 8; ks++) {
            const int k0 = ks * 8;
            float p0 = __shfl_sync(FULL, s[ks][0], srcA);
            float p1 = __shfl_sync(FULL, s[ks][1], srcA);
            float p2 = __shfl_sync(FULL, s[ks][2], srcA);
            float p3 = __shfl_sync(FULL, s[ks][3], srcA);
            float u0 = __shfl_sync(FULL, s[ks][0], srcB);
            float u1 = __shfl_sync(FULL, s[ks][1], srcB);
            float u2 = __shfl_sync(FULL, s[ks][2], srcB);
            float u3 = __shfl_sync(FULL, s[ks][3], srcB);
            unsigned a0 = f2tf(hb ? p1 : p0);
            unsigned a1 = f2tf(hb ? p3 : p2);
            unsigned a2 = f2tf(hb ? u1 : u0);
            unsigned a3 = f2tf(hb ? u3 : u2);
            #pragma unroll
            for (int nf = 0; nf < 8; nf++) {
                unsigned b0 = __float_as_uint(Vs[(k0 + j) * VSTR + nf * 8 + g]);
                unsigned b1 = __float_as_uint(Vs[(k0 + j + 4) * VSTR + nf * 8 + g]);
                mma_tf32(o[nf], a0, a1, a2, a3, b0, b1);
            }
        }

        // store prefetched V; single barrier per iteration
        if (more) {
            #pragma unroll
            for (int i = 0; i < 2; i++) {
                const int r = kr + i * 32;
                *(float4*)(Vn + r * VSTR + kc4 * 4) = cvt4(rv[i]);
            }
        }
        __syncthreads();
        cur ^= 1;
    }

    // normalize + write to [B*S, 768] attn scratch
    const float inv0 = 1.f / l0r;
    const float inv1 = 1.f / l1r;
    const int b_ = bh / NHEADS, h_ = bh % NHEADS;
    const int row0 = q0 + warp * 16 + g;
    const size_t obase = ((size_t)b_ * SEQ) * DMODEL + (size_t)h_ * DK;
    #pragma unroll
    for (int nf = 0; nf < 8; nf++) {
        const int c = nf * 8 + j * 2;
        *(float2*)(gout + obase + (size_t)row0 * DMODEL + c) =
            make_float2(o[nf][0] * inv0, o[nf][1] * inv0);
        *(float2*)(gout + obase + (size_t)(row0 + 8) * DMODEL + c) =
            make_float2(o[nf][2] * inv1, o[nf][3] * inv1);
    }
}

// ---------------- launch ----------------
extern "C" void kernel_launch(void* const* d_in, const int* in_sizes, int n_in,
                              void* d_out, int out_size)
{
    (void)in_sizes; (void)n_in; (void)out_size;
    const float* Q  = (const float*)d_in[0];
    const float* K  = (const float*)d_in[1];
    const float* V  = (const float*)d_in[2];
    const float* Wq = (const float*)d_in[3];
    const float* bq = (const float*)d_in[4];
    const float* Wk = (const float*)d_in[5];
    const float* bk = (const float*)d_in[6];
    const float* Wv = (const float*)d_in[7];
    const float* bv = (const float*)d_in[8];
    const float* Wo = (const float*)d_in[9];
    const float* bo = (const float*)d_in[10];
    float* out = (float*)d_out;

    float *pq, *pk, *pv, *pa;
    cudaGetSymbolAddress((void**)&pq, g_q);
    cudaGetSymbolAddress((void**)&pk, g_k);
    cudaGetSymbolAddress((void**)&pv, g_v);
    cudaGetSymbolAddress((void**)&pa, g_attn);

    cudaFuncSetAttribute(gemm_qkv,
                         cudaFuncAttributeMaxDynamicSharedMemorySize, GEMM_SMEM_BYTES);
    cudaFuncSetAttribute(gemm_out,
                         cudaFuncAttributeMaxDynamicSharedMemorySize, GEMM_SMEM_BYTES);
    cudaFuncSetAttribute(attn_kernel,
                         cudaFuncAttributeMaxDynamicSharedMemorySize, ATT_SMEM_BYTES);

    // Fused Q/K/V projections: grid (64, 6, 3) -> 1152 CTAs, single wave-tail.
    dim3 qkvgrid(MTOT / GTM, DMODEL / GTN, 3);
    gemm_qkv<<<qkvgrid, 256, GEMM_SMEM_BYTES>>>(Q, Wq, bq, pq,
                                                K, Wk, bk, pk,
                                                V, Wv, bv, pv);

    attn_kernel<<<dim3(SEQ / BM, BATCH * NHEADS), ATT_THREADS, ATT_SMEM_BYTES>>>(pq, pk, pv, pa);

    dim3 ogrid(MTOT / GTM, DMODEL / GTN);   // (64, 6)
    gemm_out<<<ogrid, 256, GEMM_SMEM_BYTES>>>(pa, Wo, bo, out);
}